// round 1
// baseline (speedup 1.0000x reference)
#include <cuda_runtime.h>
#include <cuda_bf16.h>

// Problem constants
#define BB 4
#define TT 64
#define LL 128
#define DD 768
#define HH 12
#define DH 64

// Device scratch for K/V projections (allocation-free per harness rules)
__device__ float g_K[BB * TT * DD];
__device__ float g_V[BB * TT * DD];

// ---------------------------------------------------------------------------
// Kernel 1: K = E @ Wk^T, V = E @ Wv^T   (E: [256,768], W: [768,768])
// grid (16 row-tiles of 16, 6 col-tiles of 128, 2 {K,V}), 256 threads
// ---------------------------------------------------------------------------
__global__ __launch_bounds__(256) void kv_proj_kernel(
    const float* __restrict__ E,
    const float* __restrict__ Wk,
    const float* __restrict__ Wv)
{
    const float* W = (blockIdx.z == 0) ? Wk : Wv;
    float* O = (blockIdx.z == 0) ? g_K : g_V;
    const int mt = blockIdx.x;   // row tile (16 rows)
    const int nt = blockIdx.y;   // col tile (128 cols)

    __shared__ float Es[32][17];    // [k][row]
    __shared__ float Ws[32][132];   // [k][col]

    const int tid = threadIdx.x;
    const int ty = tid >> 4;     // 0..15 -> output row
    const int tx = tid & 15;     // 0..15 -> 8-col group

    float acc[8];
#pragma unroll
    for (int j = 0; j < 8; j++) acc[j] = 0.f;

    for (int k0 = 0; k0 < DD; k0 += 32) {
        if (tid < 128) {                       // 16 rows x 8 float4
            int r = tid >> 3, c4 = tid & 7;
            float4 v = *(const float4*)&E[(size_t)(mt * 16 + r) * DD + k0 + c4 * 4];
            Es[c4 * 4 + 0][r] = v.x; Es[c4 * 4 + 1][r] = v.y;
            Es[c4 * 4 + 2][r] = v.z; Es[c4 * 4 + 3][r] = v.w;
        }
#pragma unroll
        for (int it = 0; it < 4; it++) {       // 128 rows x 8 float4
            int idx = tid + it * 256;
            int r = idx >> 3, c4 = idx & 7;
            float4 v = *(const float4*)&W[(size_t)(nt * 128 + r) * DD + k0 + c4 * 4];
            Ws[c4 * 4 + 0][r] = v.x; Ws[c4 * 4 + 1][r] = v.y;
            Ws[c4 * 4 + 2][r] = v.z; Ws[c4 * 4 + 3][r] = v.w;
        }
        __syncthreads();
#pragma unroll
        for (int kk = 0; kk < 32; kk++) {
            float e = Es[kk][ty];
            float w[8];
            *(float4*)&w[0] = *(const float4*)&Ws[kk][tx * 8];
            *(float4*)&w[4] = *(const float4*)&Ws[kk][tx * 8 + 4];
#pragma unroll
            for (int j = 0; j < 8; j++) acc[j] = fmaf(e, w[j], acc[j]);
        }
        __syncthreads();
    }

    float* orow = &O[(size_t)(mt * 16 + ty) * DD + nt * 128 + tx * 8];
    *(float4*)&orow[0] = make_float4(acc[0], acc[1], acc[2], acc[3]);
    *(float4*)&orow[4] = make_float4(acc[4], acc[5], acc[6], acc[7]);
}

// ---------------------------------------------------------------------------
// Kernel 2: fused per (b,t,h):
//   Q = X[b,t] @ Wq_h^T          [128 x 64], K = 768
//   S = Q @ (mask .* K_h)^T      [128 x 64]
//   A = S @ V_h                  [128 x 64]
//   out[:, h*64:(h+1)*64] = X[:, h*64:(h+1)*64] + A
// 256 threads as 16(ty) x 16(tx); thread tile 8 rows x 4 cols.
// ---------------------------------------------------------------------------
#define ASW 132   // As row pitch (padded)
#define BSW 68    // Bs row pitch
#define QSW 132   // Qst/Sst row pitch
#define KSW 68
#define VSW 68

// union region: max(32*ASW + 32*BSW, 64*QSW) = max(6400, 8448) = 8448 floats
#define UNION_F 8448
#define SMEM_F  (UNION_F + 64 * KSW + 64 * VSW)
#define SMEM_BYTES (SMEM_F * 4)

__global__ __launch_bounds__(256) void saute_main_kernel(
    const float* __restrict__ X,
    const int*   __restrict__ spk,
    const float* __restrict__ Wq,
    float*       __restrict__ Out)
{
    extern __shared__ float sm[];
    float* As  = sm;                  // [32][ASW] (phase 1)
    float* Bs  = sm + 32 * ASW;       // [32][BSW] (phase 1)
    float* Qst = sm;                  // [64][QSW] (phases 2,3; union w/ As+Bs)
    float* Ks  = sm + UNION_F;        // [64][KSW]  Ks[d][u] (mask folded in)
    float* Vs  = Ks + 64 * KSW;       // [64][VSW]  Vs[u][e]

    const int h = blockIdx.x, t = blockIdx.y, b = blockIdx.z;
    const int tid = threadIdx.x;
    const int ty = tid >> 4, tx = tid & 15;

    const float* Xb  = X  + ((size_t)(b * TT + t)) * LL * DD;
    const float* Wqh = Wq + (size_t)h * DH * DD;

    // ---- load masked K_h (transposed) and V_h into smem ----
    const int spk_t = spk[b * TT + t];
#pragma unroll
    for (int it = 0; it < 4; it++) {
        int idx = tid + it * 256;          // 1024 float4 units: 64 u x 16
        int u = idx >> 4, c4 = idx & 15;
        size_t g = (size_t)(b * TT + u) * DD + h * DH + c4 * 4;
        float m = (u <= t && spk[b * TT + u] == spk_t) ? 1.f : 0.f;
        float4 kv = *(const float4*)&g_K[g];
        Ks[(c4 * 4 + 0) * KSW + u] = kv.x * m;
        Ks[(c4 * 4 + 1) * KSW + u] = kv.y * m;
        Ks[(c4 * 4 + 2) * KSW + u] = kv.z * m;
        Ks[(c4 * 4 + 3) * KSW + u] = kv.w * m;
        float4 vv = *(const float4*)&g_V[g];
        *(float4*)&Vs[u * VSW + c4 * 4] = vv;
    }
    // visibility of Ks/Vs ensured by the first __syncthreads below

    // ---- Phase 1: Q = Xb @ Wqh^T (register tiled, K chunks of 32) ----
    float q[8][4];
#pragma unroll
    for (int i = 0; i < 8; i++)
#pragma unroll
        for (int j = 0; j < 4; j++) q[i][j] = 0.f;

    for (int k0 = 0; k0 < DD; k0 += 32) {
#pragma unroll
        for (int it = 0; it < 4; it++) {   // X chunk: 128 l x 8 float4
            int idx = tid + it * 256;
            int l = idx >> 3, c4 = idx & 7;
            float4 v = *(const float4*)&Xb[(size_t)l * DD + k0 + c4 * 4];
            As[(c4 * 4 + 0) * ASW + l] = v.x;
            As[(c4 * 4 + 1) * ASW + l] = v.y;
            As[(c4 * 4 + 2) * ASW + l] = v.z;
            As[(c4 * 4 + 3) * ASW + l] = v.w;
        }
#pragma unroll
        for (int it = 0; it < 2; it++) {   // Wq chunk: 64 j x 8 float4
            int idx = tid + it * 256;
            int j = idx >> 3, c4 = idx & 7;
            float4 v = *(const float4*)&Wqh[(size_t)j * DD + k0 + c4 * 4];
            Bs[(c4 * 4 + 0) * BSW + j] = v.x;
            Bs[(c4 * 4 + 1) * BSW + j] = v.y;
            Bs[(c4 * 4 + 2) * BSW + j] = v.z;
            Bs[(c4 * 4 + 3) * BSW + j] = v.w;
        }
        __syncthreads();
#pragma unroll
        for (int kk = 0; kk < 32; kk++) {
            float a[8], w[4];
            *(float4*)&a[0] = *(const float4*)&As[kk * ASW + ty * 8];
            *(float4*)&a[4] = *(const float4*)&As[kk * ASW + ty * 8 + 4];
            *(float4*)&w[0] = *(const float4*)&Bs[kk * BSW + tx * 4];
#pragma unroll
            for (int i = 0; i < 8; i++)
#pragma unroll
                for (int j = 0; j < 4; j++)
                    q[i][j] = fmaf(a[i], w[j], q[i][j]);
        }
        __syncthreads();
    }

    // ---- Phase 2: S = Q @ Ks (mask already folded into Ks) ----
    // write Q transposed into Qst (safe: last __syncthreads above)
#pragma unroll
    for (int i = 0; i < 8; i++)
#pragma unroll
        for (int j = 0; j < 4; j++)
            Qst[(tx * 4 + j) * QSW + ty * 8 + i] = q[i][j];
    __syncthreads();

    float s[8][4];
#pragma unroll
    for (int i = 0; i < 8; i++)
#pragma unroll
        for (int j = 0; j < 4; j++) s[i][j] = 0.f;
#pragma unroll 8
    for (int dd = 0; dd < 64; dd++) {
        float a[8], w[4];
        *(float4*)&a[0] = *(const float4*)&Qst[dd * QSW + ty * 8];
        *(float4*)&a[4] = *(const float4*)&Qst[dd * QSW + ty * 8 + 4];
        *(float4*)&w[0] = *(const float4*)&Ks[dd * KSW + tx * 4];
#pragma unroll
        for (int i = 0; i < 8; i++)
#pragma unroll
            for (int j = 0; j < 4; j++)
                s[i][j] = fmaf(a[i], w[j], s[i][j]);
    }
    __syncthreads();

    // ---- Phase 3: A = S @ Vs ----
#pragma unroll
    for (int i = 0; i < 8; i++)
#pragma unroll
        for (int j = 0; j < 4; j++)
            Qst[(tx * 4 + j) * QSW + ty * 8 + i] = s[i][j];   // Sst (reuse)
    __syncthreads();

    float o[8][4];
#pragma unroll
    for (int i = 0; i < 8; i++)
#pragma unroll
        for (int j = 0; j < 4; j++) o[i][j] = 0.f;
#pragma unroll 8
    for (int u = 0; u < 64; u++) {
        float a[8], w[4];
        *(float4*)&a[0] = *(const float4*)&Qst[u * QSW + ty * 8];
        *(float4*)&a[4] = *(const float4*)&Qst[u * QSW + ty * 8 + 4];
        *(float4*)&w[0] = *(const float4*)&Vs[u * VSW + tx * 4];
#pragma unroll
        for (int i = 0; i < 8; i++)
#pragma unroll
            for (int j = 0; j < 4; j++)
                o[i][j] = fmaf(a[i], w[j], o[i][j]);
    }

    // ---- Phase 4: out = X + A (this head's 64 columns) ----
    float* Ob = Out + ((size_t)(b * TT + t)) * LL * DD;
#pragma unroll
    for (int i = 0; i < 8; i++) {
        int l = ty * 8 + i;
        size_t g = (size_t)l * DD + h * DH + tx * 4;
        float4 x = *(const float4*)&Xb[g];
        float4 r = make_float4(x.x + o[i][0], x.y + o[i][1],
                               x.z + o[i][2], x.w + o[i][3]);
        *(float4*)&Ob[g] = r;
    }
}

// ---------------------------------------------------------------------------
// kernel_launch: inputs in metadata order:
// 0 input_ids (unused), 1 speaker_ids, 2 token_embeddings, 3 edu_embeddings,
// 4 Wk, 5 Wv, 6 Wq. Output: float32 [B,T,L,D].
// ---------------------------------------------------------------------------
extern "C" void kernel_launch(void* const* d_in, const int* in_sizes, int n_in,
                              void* d_out, int out_size)
{
    (void)in_sizes; (void)n_in; (void)out_size;
    const int*   spk = (const int*)d_in[1];
    const float* X   = (const float*)d_in[2];
    const float* E   = (const float*)d_in[3];
    const float* Wk  = (const float*)d_in[4];
    const float* Wv  = (const float*)d_in[5];
    const float* Wq  = (const float*)d_in[6];
    float* out = (float*)d_out;

    kv_proj_kernel<<<dim3(16, 6, 2), 256>>>(E, Wk, Wv);

    cudaFuncSetAttribute(saute_main_kernel,
                         cudaFuncAttributeMaxDynamicSharedMemorySize, SMEM_BYTES);
    saute_main_kernel<<<dim3(HH, TT, BB), 256, SMEM_BYTES>>>(X, spk, Wq, out);
}

// round 4
// speedup vs baseline: 2.0567x; 2.0567x over previous
#include <cuda_runtime.h>
#include <cuda_bf16.h>
#include <cstdint>

// ---------------------------------------------------------------------------
// Problem constants
// ---------------------------------------------------------------------------
#define BB 4
#define TT 64
#define LL 128
#define DD 768
#define HH 12
#define DH 64
#define MROWS (BB * TT * LL)     // 32768

// ---------------------------------------------------------------------------
// Device scratch (allocation-free per harness rules)
// ---------------------------------------------------------------------------
__device__ __align__(16) __nv_bfloat16 g_Xhi[MROWS * DD];
__device__ __align__(16) __nv_bfloat16 g_Xlo[MROWS * DD];
__device__ __align__(16) __nv_bfloat16 g_Wqhi[DD * DD];
__device__ __align__(16) __nv_bfloat16 g_Wqlo[DD * DD];
__device__ __align__(16) __nv_bfloat16 g_Qhi[MROWS * DD];
__device__ __align__(16) __nv_bfloat16 g_Qlo[MROWS * DD];
// K split:  [B][H][u][d],  V transposed split: [B][H][e][u]
__device__ __align__(16) __nv_bfloat16 g_Khi[BB * HH * DH * DH];
__device__ __align__(16) __nv_bfloat16 g_Klo[BB * HH * DH * DH];
__device__ __align__(16) __nv_bfloat16 g_Vthi[BB * HH * DH * DH];
__device__ __align__(16) __nv_bfloat16 g_Vtlo[BB * HH * DH * DH];

// ---------------------------------------------------------------------------
// Helpers (sm_80-era ISA only: ldmatrix / mma.sync / cp.async — valid on sm_100)
// ---------------------------------------------------------------------------
__device__ __forceinline__ uint32_t smem_u32(const void* p) {
    uint32_t a;
    asm("{ .reg .u64 t; cvta.to.shared.u64 t, %1; cvt.u32.u64 %0, t; }" : "=r"(a) : "l"(p));
    return a;
}
#define SWZ(off) ((off) ^ (((off) >> 3) & 0x70))

__device__ __forceinline__ void ldsm4(uint32_t* r, uint32_t a) {
    asm volatile("ldmatrix.sync.aligned.m8n8.x4.shared.b16 {%0,%1,%2,%3}, [%4];"
                 : "=r"(r[0]), "=r"(r[1]), "=r"(r[2]), "=r"(r[3]) : "r"(a));
}

// D = A(16x16 bf16, row) * B(16x8 bf16, col) + D, fp32 accum
__device__ __forceinline__ void mma16816(float* c, const uint32_t* a, const uint32_t* b) {
    asm volatile(
        "mma.sync.aligned.m16n8k16.row.col.f32.bf16.bf16.f32 "
        "{%0,%1,%2,%3}, {%4,%5,%6,%7}, {%8,%9}, {%0,%1,%2,%3};"
        : "+f"(c[0]), "+f"(c[1]), "+f"(c[2]), "+f"(c[3])
        : "r"(a[0]), "r"(a[1]), "r"(a[2]), "r"(a[3]), "r"(b[0]), "r"(b[1]));
}

__device__ __forceinline__ void cp_async16(uint32_t saddr, const void* gptr) {
    asm volatile("cp.async.cg.shared.global [%0], [%1], 16;" :: "r"(saddr), "l"(gptr));
}
#define CP_COMMIT() asm volatile("cp.async.commit_group;" ::: "memory")
#define CP_WAIT0()  asm volatile("cp.async.wait_group 0;" ::: "memory")
#define CP_WAIT1()  asm volatile("cp.async.wait_group 1;" ::: "memory")

__device__ __forceinline__ uint32_t pack_bf16(__nv_bfloat16 a, __nv_bfloat16 b) {
    __nv_bfloat162 p; p.x = a; p.y = b;
    return *reinterpret_cast<uint32_t*>(&p);
}
__device__ __forceinline__ void split32(float v, __nv_bfloat16& h, __nv_bfloat16& l) {
    h = __float2bfloat16_rn(v);
    l = __float2bfloat16_rn(v - __bfloat162float(h));
}

// ---------------------------------------------------------------------------
// Kernel 0a/0b: fp32 -> bf16 hi/lo split
// ---------------------------------------------------------------------------
__global__ __launch_bounds__(256) void convert_X_kernel(const float4* __restrict__ src)
{
    int i = blockIdx.x * blockDim.x + threadIdx.x;
    const int n4 = MROWS * DD / 4;
    if (i >= n4) return;
    float4 v = src[i];
    __nv_bfloat16 h0, l0, h1, l1, h2, l2, h3, l3;
    split32(v.x, h0, l0); split32(v.y, h1, l1);
    split32(v.z, h2, l2); split32(v.w, h3, l3);
    *reinterpret_cast<uint2*>(g_Xhi + (size_t)i * 4) =
        make_uint2(pack_bf16(h0, h1), pack_bf16(h2, h3));
    *reinterpret_cast<uint2*>(g_Xlo + (size_t)i * 4) =
        make_uint2(pack_bf16(l0, l1), pack_bf16(l2, l3));
}

__global__ __launch_bounds__(256) void convert_W_kernel(const float4* __restrict__ src)
{
    int i = blockIdx.x * blockDim.x + threadIdx.x;
    const int n4 = DD * DD / 4;
    if (i >= n4) return;
    float4 v = src[i];
    __nv_bfloat16 h0, l0, h1, l1, h2, l2, h3, l3;
    split32(v.x, h0, l0); split32(v.y, h1, l1);
    split32(v.z, h2, l2); split32(v.w, h3, l3);
    *reinterpret_cast<uint2*>(g_Wqhi + (size_t)i * 4) =
        make_uint2(pack_bf16(h0, h1), pack_bf16(h2, h3));
    *reinterpret_cast<uint2*>(g_Wqlo + (size_t)i * 4) =
        make_uint2(pack_bf16(l0, l1), pack_bf16(l2, l3));
}

// ---------------------------------------------------------------------------
// Kernel 1: K/V projections fp32 SIMT; epilogue writes split K / V^T tiles
// E: [256,768], W: [768,768]; grid (16,6,2), 256 threads
// ---------------------------------------------------------------------------
__global__ __launch_bounds__(256) void kv_proj_kernel(
    const float* __restrict__ E,
    const float* __restrict__ Wk,
    const float* __restrict__ Wv)
{
    const int isV = blockIdx.z;
    const float* W = isV ? Wv : Wk;
    const int mt = blockIdx.x, nt = blockIdx.y;

    __shared__ float Es[32][17];
    __shared__ float Ws[32][132];

    const int tid = threadIdx.x;
    const int ty = tid >> 4, tx = tid & 15;

    float acc[8];
#pragma unroll
    for (int j = 0; j < 8; j++) acc[j] = 0.f;

    for (int k0 = 0; k0 < DD; k0 += 32) {
        if (tid < 128) {
            int r = tid >> 3, c4 = tid & 7;
            float4 v = *(const float4*)&E[(size_t)(mt * 16 + r) * DD + k0 + c4 * 4];
            Es[c4 * 4 + 0][r] = v.x; Es[c4 * 4 + 1][r] = v.y;
            Es[c4 * 4 + 2][r] = v.z; Es[c4 * 4 + 3][r] = v.w;
        }
#pragma unroll
        for (int it = 0; it < 4; it++) {
            int idx = tid + it * 256;
            int r = idx >> 3, c4 = idx & 7;
            float4 v = *(const float4*)&W[(size_t)(nt * 128 + r) * DD + k0 + c4 * 4];
            Ws[c4 * 4 + 0][r] = v.x; Ws[c4 * 4 + 1][r] = v.y;
            Ws[c4 * 4 + 2][r] = v.z; Ws[c4 * 4 + 3][r] = v.w;
        }
        __syncthreads();
#pragma unroll
        for (int kk = 0; kk < 32; kk++) {
            float e = Es[kk][ty];
            float w[8];
            *(float4*)&w[0] = *(const float4*)&Ws[kk][tx * 8];
            *(float4*)&w[4] = *(const float4*)&Ws[kk][tx * 8 + 4];
#pragma unroll
            for (int j = 0; j < 8; j++) acc[j] = fmaf(e, w[j], acc[j]);
        }
        __syncthreads();
    }

    const int r = mt * 16 + ty;
    const int b = r >> 6, u = r & 63;
    const int c0 = nt * 128 + tx * 8;
    const int h = c0 >> 6, d0 = c0 & 63;
    const int tilebase = ((b * HH + h) * DH) * DH;
#pragma unroll
    for (int j = 0; j < 8; j++) {
        __nv_bfloat16 hi, lo;
        split32(acc[j], hi, lo);
        if (!isV) {
            int idx = tilebase + u * DH + (d0 + j);
            g_Khi[idx] = hi; g_Klo[idx] = lo;
        } else {
            int idx = tilebase + (d0 + j) * DH + u;
            g_Vthi[idx] = hi; g_Vtlo[idx] = lo;
        }
    }
}

// ---------------------------------------------------------------------------
// Kernel 2: Q = X @ Wq^T via mma.sync bf16 hi/lo 3-pass.
// M=32768, N=768, K=768. CTA 128x128, K-chunk 64, double-buffered cp.async.
// 256 threads = 8 warps as 4(M) x 2(N); warp tile 32x64.
// smem stage: Ahi|Alo|Bhi|Blo, each [128][64] bf16, SW128 rows of 128B.
// ---------------------------------------------------------------------------
#define QG_TILE  16384
#define QG_STAGE (4 * QG_TILE)    // 64 KB
#define QG_SMEM  (2 * QG_STAGE)   // 128 KB

__device__ __forceinline__ void qg_load(
    int s, int tid, uint32_t base,
    const __nv_bfloat16* Ah, const __nv_bfloat16* Al,
    const __nv_bfloat16* Bh, const __nv_bfloat16* Bl)
{
    const int k0 = s * 64;
    const uint32_t buf = base + (s & 1) * QG_STAGE;
#pragma unroll
    for (int i = 0; i < 4; i++) {
        int idx = tid + i * 256;          // 1024 16B units: 128 rows x 8
        int r = idx >> 3, c = idx & 7;
        uint32_t sw = SWZ(r * 128 + c * 16);
        size_t g = (size_t)r * DD + k0 + c * 8;
        cp_async16(buf + sw,                Ah + g);
        cp_async16(buf + QG_TILE + sw,      Al + g);
        cp_async16(buf + 2 * QG_TILE + sw,  Bh + g);
        cp_async16(buf + 3 * QG_TILE + sw,  Bl + g);
    }
    CP_COMMIT();
}

__global__ __launch_bounds__(256) void q_gemm_kernel()
{
    extern __shared__ char sm[];
    const uint32_t base = smem_u32(sm);
    const int tid = threadIdx.x, lane = tid & 31, wid = tid >> 5;
    const int wm = wid & 3, wn = wid >> 2;
    const int nt_b = blockIdx.x, mt_b = blockIdx.y;
    const size_t mrow0 = (size_t)mt_b * 128;
    const int n0 = nt_b * 128;

    const __nv_bfloat16* Ah = g_Xhi  + mrow0 * DD;
    const __nv_bfloat16* Al = g_Xlo  + mrow0 * DD;
    const __nv_bfloat16* Bh = g_Wqhi + (size_t)n0 * DD;
    const __nv_bfloat16* Bl = g_Wqlo + (size_t)n0 * DD;

    float acc[2][8][4];
#pragma unroll
    for (int mt = 0; mt < 2; mt++)
#pragma unroll
        for (int nt = 0; nt < 8; nt++)
#pragma unroll
            for (int j = 0; j < 4; j++) acc[mt][nt][j] = 0.f;

    qg_load(0, tid, base, Ah, Al, Bh, Bl);
    qg_load(1, tid, base, Ah, Al, Bh, Bl);

    const int li = lane & 7, mi = lane >> 3;
    // ldmatrix lane-address components (per PTX m16n8k16 fragment layouts):
    const int a_row = li + (mi & 1) * 8;          // + R0
    const int a_cb  = (mi >> 1) * 16;             // + k0*2
    const int b_row = li + (mi >> 1) * 8;         // + N0
    const int b_cb  = (mi & 1) * 16;              // + k0*2

    for (int s = 0; s < 12; s++) {
        if (s == 11) CP_WAIT0(); else CP_WAIT1();
        __syncthreads();
        const uint32_t bA  = base + (s & 1) * QG_STAGE;
        const uint32_t bAl = bA + QG_TILE;
        const uint32_t bB  = bA + 2 * QG_TILE;
        const uint32_t bBl = bA + 3 * QG_TILE;

#pragma unroll
        for (int ks = 0; ks < 4; ks++) {
            const int kb = ks * 32;   // byte offset of k0 in 128B row
            uint32_t ah[2][4], al2[2][4];
#pragma unroll
            for (int mt = 0; mt < 2; mt++) {
                uint32_t off = SWZ((wm * 32 + mt * 16 + a_row) * 128 + kb + a_cb);
                ldsm4(ah[mt],  bA  + off);
                ldsm4(al2[mt], bAl + off);
            }
            uint32_t bh[8][2], bl2[8][2];
#pragma unroll
            for (int bt = 0; bt < 4; bt++) {
                uint32_t off = SWZ((wn * 64 + bt * 16 + b_row) * 128 + kb + b_cb);
                uint32_t t4[4];
                ldsm4(t4, bB + off);
                bh[2 * bt][0] = t4[0]; bh[2 * bt][1] = t4[1];
                bh[2 * bt + 1][0] = t4[2]; bh[2 * bt + 1][1] = t4[3];
                ldsm4(t4, bBl + off);
                bl2[2 * bt][0] = t4[0]; bl2[2 * bt][1] = t4[1];
                bl2[2 * bt + 1][0] = t4[2]; bl2[2 * bt + 1][1] = t4[3];
            }
#pragma unroll
            for (int mt = 0; mt < 2; mt++)
#pragma unroll
                for (int nt = 0; nt < 8; nt++) {
                    mma16816(acc[mt][nt], ah[mt],  bh[nt]);
                    mma16816(acc[mt][nt], ah[mt],  bl2[nt]);
                    mma16816(acc[mt][nt], al2[mt], bh[nt]);
                }
        }
        __syncthreads();
        if (s + 2 < 12) qg_load(s + 2, tid, base, Ah, Al, Bh, Bl);
    }

    // epilogue: acc -> bf16 hi/lo -> g_Qhi/g_Qlo
    const int q2 = 2 * (lane & 3);
#pragma unroll
    for (int mt = 0; mt < 2; mt++) {
        const int r0 = wm * 32 + mt * 16 + (lane >> 2);
#pragma unroll
        for (int nt = 0; nt < 8; nt++) {
            const int col = n0 + wn * 64 + nt * 8 + q2;
            __nv_bfloat16 h0, l0, h1, l1, h2, l2, h3, l3;
            split32(acc[mt][nt][0], h0, l0);
            split32(acc[mt][nt][1], h1, l1);
            split32(acc[mt][nt][2], h2, l2);
            split32(acc[mt][nt][3], h3, l3);
            *reinterpret_cast<uint32_t*>(g_Qhi + (mrow0 + r0)     * DD + col) = pack_bf16(h0, h1);
            *reinterpret_cast<uint32_t*>(g_Qlo + (mrow0 + r0)     * DD + col) = pack_bf16(l0, l1);
            *reinterpret_cast<uint32_t*>(g_Qhi + (mrow0 + r0 + 8) * DD + col) = pack_bf16(h2, h3);
            *reinterpret_cast<uint32_t*>(g_Qlo + (mrow0 + r0 + 8) * DD + col) = pack_bf16(l2, l3);
        }
    }
}

// ---------------------------------------------------------------------------
// Kernel 3: attention per (t, h, b). 128 threads = 4 warps, warp = 32 rows.
//   S = Q @ K^T (mma), mask+split in registers, A = S @ V (mma), out = X + A.
// smem: Qhi 16K | Qlo 16K | Khi 8K | Klo 8K | Vthi 8K | Vtlo 8K | spk 256B
// ---------------------------------------------------------------------------
#define AT_QHI   0
#define AT_QLO   16384
#define AT_KHI   32768
#define AT_KLO   40960
#define AT_VHI   49152
#define AT_VLO   57344
#define AT_SPK   65536
#define AT_SMEM  (AT_SPK + 256)

__global__ __launch_bounds__(128) void attn_kernel(
    const float* __restrict__ X,
    const int*   __restrict__ spk,
    float*       __restrict__ Out)
{
    extern __shared__ char sm[];
    const uint32_t base = smem_u32(sm);
    const int tid = threadIdx.x, lane = tid & 31, wid = tid >> 5;
    const int t = blockIdx.x, h = blockIdx.y, b = blockIdx.z;

    int* spk_s = reinterpret_cast<int*>(sm + AT_SPK);
    if (tid < TT) spk_s[tid] = spk[b * TT + tid];

    const size_t qbase = ((size_t)(b * TT + t) * LL) * DD + h * DH;
    const int kvbase = ((b * HH + h) * DH) * DH;

#pragma unroll
    for (int i = 0; i < 8; i++) {             // Q hi/lo: 128 rows x 8 16B-units
        int idx = tid + i * 128;
        int r = idx >> 3, c = idx & 7;
        uint32_t sw = SWZ(r * 128 + c * 16);
        size_t g = qbase + (size_t)r * DD + c * 8;
        cp_async16(base + AT_QHI + sw, g_Qhi + g);
        cp_async16(base + AT_QLO + sw, g_Qlo + g);
    }
#pragma unroll
    for (int i = 0; i < 4; i++) {             // K, Vt hi/lo: 64 rows x 8 units
        int idx = tid + i * 128;
        int r = idx >> 3, c = idx & 7;
        uint32_t sw = SWZ(r * 128 + c * 16);
        int g = kvbase + r * DH + c * 8;
        cp_async16(base + AT_KHI + sw, g_Khi + g);
        cp_async16(base + AT_KLO + sw, g_Klo + g);
        cp_async16(base + AT_VHI + sw, g_Vthi + g);
        cp_async16(base + AT_VLO + sw, g_Vtlo + g);
    }
    CP_COMMIT();
    CP_WAIT0();
    __syncthreads();

    const int spk_t = spk_s[t];
    const int li = lane & 7, mi = lane >> 3;
    const int a_row = li + (mi & 1) * 8;
    const int a_cb  = (mi >> 1) * 16;
    const int b_row = li + (mi >> 1) * 8;
    const int b_cb  = (mi & 1) * 16;
    const int q2 = 2 * (lane & 3);

    // ---- MMA1: S = Q @ K^T ----
    float acc[2][8][4];
#pragma unroll
    for (int mt = 0; mt < 2; mt++)
#pragma unroll
        for (int nt = 0; nt < 8; nt++)
#pragma unroll
            for (int j = 0; j < 4; j++) acc[mt][nt][j] = 0.f;

#pragma unroll
    for (int ks = 0; ks < 4; ks++) {
        const int kb = ks * 32;
        uint32_t qh[2][4], ql[2][4];
#pragma unroll
        for (int mt = 0; mt < 2; mt++) {
            uint32_t off = SWZ((wid * 32 + mt * 16 + a_row) * 128 + kb + a_cb);
            ldsm4(qh[mt], base + AT_QHI + off);
            ldsm4(ql[mt], base + AT_QLO + off);
        }
        uint32_t kh[8][2], kl[8][2];
#pragma unroll
        for (int bt = 0; bt < 4; bt++) {
            uint32_t off = SWZ((bt * 16 + b_row) * 128 + kb + b_cb);
            uint32_t t4[4];
            ldsm4(t4, base + AT_KHI + off);
            kh[2 * bt][0] = t4[0]; kh[2 * bt][1] = t4[1];
            kh[2 * bt + 1][0] = t4[2]; kh[2 * bt + 1][1] = t4[3];
            ldsm4(t4, base + AT_KLO + off);
            kl[2 * bt][0] = t4[0]; kl[2 * bt][1] = t4[1];
            kl[2 * bt + 1][0] = t4[2]; kl[2 * bt + 1][1] = t4[3];
        }
#pragma unroll
        for (int mt = 0; mt < 2; mt++)
#pragma unroll
            for (int nt = 0; nt < 8; nt++) {
                mma16816(acc[mt][nt], qh[mt], kh[nt]);
                mma16816(acc[mt][nt], qh[mt], kl[nt]);
                mma16816(acc[mt][nt], ql[mt], kh[nt]);
            }
    }

    // ---- mask + hi/lo split in registers ----
    // acc[mt][nt] cols (u0,u1) map directly to A-fragment regs of MMA2:
    //   sh[mt][ki=nt/2][(nt&1)*2 + {0,1}]
    uint32_t sh[2][4][4], sl[2][4][4];
#pragma unroll
    for (int nt = 0; nt < 8; nt++) {
        const int u0 = nt * 8 + q2, u1 = u0 + 1;
        const bool m0 = (u0 <= t) && (spk_s[u0] == spk_t);
        const bool m1 = (u1 <= t) && (spk_s[u1] == spk_t);
#pragma unroll
        for (int mt = 0; mt < 2; mt++) {
            float c0 = m0 ? acc[mt][nt][0] : 0.f;
            float c1 = m1 ? acc[mt][nt][1] : 0.f;
            float c2 = m0 ? acc[mt][nt][2] : 0.f;
            float c3 = m1 ? acc[mt][nt][3] : 0.f;
            __nv_bfloat16 h0, l0, h1, l1, h2, l2, h3, l3;
            split32(c0, h0, l0); split32(c1, h1, l1);
            split32(c2, h2, l2); split32(c3, h3, l3);
            sh[mt][nt >> 1][(nt & 1) * 2 + 0] = pack_bf16(h0, h1);
            sl[mt][nt >> 1][(nt & 1) * 2 + 0] = pack_bf16(l0, l1);
            sh[mt][nt >> 1][(nt & 1) * 2 + 1] = pack_bf16(h2, h3);
            sl[mt][nt >> 1][(nt & 1) * 2 + 1] = pack_bf16(l2, l3);
        }
    }

    // ---- MMA2: A = S @ V  (B operand = Vt[e][u], K = u) ----
    float acc2[2][8][4];
#pragma unroll
    for (int mt = 0; mt < 2; mt++)
#pragma unroll
        for (int et = 0; et < 8; et++)
#pragma unroll
            for (int j = 0; j < 4; j++) acc2[mt][et][j] = 0.f;

#pragma unroll
    for (int ks = 0; ks < 4; ks++) {
        const int kb = ks * 32;
        uint32_t vh[8][2], vl[8][2];
#pragma unroll
        for (int bt = 0; bt < 4; bt++) {
            uint32_t off = SWZ((bt * 16 + b_row) * 128 + kb + b_cb);
            uint32_t t4[4];
            ldsm4(t4, base + AT_VHI + off);
            vh[2 * bt][0] = t4[0]; vh[2 * bt][1] = t4[1];
            vh[2 * bt + 1][0] = t4[2]; vh[2 * bt + 1][1] = t4[3];
            ldsm4(t4, base + AT_VLO + off);
            vl[2 * bt][0] = t4[0]; vl[2 * bt][1] = t4[1];
            vl[2 * bt + 1][0] = t4[2]; vl[2 * bt + 1][1] = t4[3];
        }
#pragma unroll
        for (int mt = 0; mt < 2; mt++)
#pragma unroll
            for (int et = 0; et < 8; et++) {
                mma16816(acc2[mt][et], sh[mt][ks], vh[et]);
                mma16816(acc2[mt][et], sh[mt][ks], vl[et]);
                mma16816(acc2[mt][et], sl[mt][ks], vh[et]);
            }
    }

    // ---- epilogue: out = X + A ----
#pragma unroll
    for (int mt = 0; mt < 2; mt++) {
        const int r0 = wid * 32 + mt * 16 + (lane >> 2);
#pragma unroll
        for (int et = 0; et < 8; et++) {
            const int co = et * 8 + q2;
            {
                const size_t g = qbase + (size_t)r0 * DD + co;
                float2 x = *reinterpret_cast<const float2*>(X + g);
                float2 o = make_float2(x.x + acc2[mt][et][0], x.y + acc2[mt][et][1]);
                *reinterpret_cast<float2*>(Out + g) = o;
            }
            {
                const size_t g = qbase + (size_t)(r0 + 8) * DD + co;
                float2 x = *reinterpret_cast<const float2*>(X + g);
                float2 o = make_float2(x.x + acc2[mt][et][2], x.y + acc2[mt][et][3]);
                *reinterpret_cast<float2*>(Out + g) = o;
            }
        }
    }
}

// ---------------------------------------------------------------------------
// kernel_launch: inputs: 0 input_ids (unused), 1 speaker_ids,
// 2 token_embeddings, 3 edu_embeddings, 4 Wk, 5 Wv, 6 Wq. Output fp32.
// ---------------------------------------------------------------------------
extern "C" void kernel_launch(void* const* d_in, const int* in_sizes, int n_in,
                              void* d_out, int out_size)
{
    (void)in_sizes; (void)n_in; (void)out_size;
    const int*   spk = (const int*)d_in[1];
    const float* X   = (const float*)d_in[2];
    const float* E   = (const float*)d_in[3];
    const float* Wk  = (const float*)d_in[4];
    const float* Wv  = (const float*)d_in[5];
    const float* Wq  = (const float*)d_in[6];
    float* out = (float*)d_out;

    const int nx4 = MROWS * DD / 4;
    const int nw4 = DD * DD / 4;
    convert_X_kernel<<<(nx4 + 255) / 256, 256>>>((const float4*)X);
    convert_W_kernel<<<(nw4 + 255) / 256, 256>>>((const float4*)Wq);

    kv_proj_kernel<<<dim3(16, 6, 2), 256>>>(E, Wk, Wv);

    cudaFuncSetAttribute(q_gemm_kernel,
                         cudaFuncAttributeMaxDynamicSharedMemorySize, QG_SMEM);
    cudaFuncSetAttribute(attn_kernel,
                         cudaFuncAttributeMaxDynamicSharedMemorySize, AT_SMEM);

    q_gemm_kernel<<<dim3(6, 256), 256, QG_SMEM>>>();
    attn_kernel<<<dim3(TT, HH, BB), 128, AT_SMEM>>>(X, spk, out);
}